// round 15
// baseline (speedup 1.0000x reference)
#include <cuda_runtime.h>
#include <cuda_fp16.h>
#include <math.h>
#include <stdint.h>

#define NN 10000
#define EE 320000
#define CAP 192   // bucket slots per node; deg ~ Binom(320k, 1e-4), mean 32, P(>192) ~ 0
#define NTIL 632  // 79 row tiles x 8 col tiles
#define GRID_MMA 592  // 148 SMs x 2 CTAs x 2 waves exactly

// ---------------- scratch (static device globals; no allocation) ----------------
__device__ int   g_cnt[NN];                   // zero-init at load; k_agg re-zeros after use
__device__ int   g_bucket[(size_t)NN * CAP];  // per-node src lists
__device__ __half g_Ab[(size_t)NN * 1024];    // [aggX | X | aggH | h] fp16
__device__ __half g_Wtb[(size_t)1024 * 1024]; // W^T: row j'(out col), K contiguous
__device__ float g_bias[1024];                // bx_l + bh_l + b, in j' order

__device__ __forceinline__ uint32_t smem_u32(const void* p) {
    uint32_t a;
    asm("{ .reg .u64 t; cvta.to.shared.u64 t, %1; cvt.u32.u64 %0, t; }" : "=r"(a) : "l"(p));
    return a;
}

// ---------------- fused edge pass: dtype detect + scatter into buckets ----------------
__global__ void k_edges(const void* __restrict__ ei) {
    __shared__ int is64_s;
    if (threadIdx.x == 0) {
        const unsigned* w = (const unsigned*)ei;
        unsigned bad = 0;
        #pragma unroll
        for (int k = 0; k < 64; k++) bad |= w[2 * k + 1];  // high words if int64
        is64_s = (bad == 0) ? 1 : 0;
    }
    __syncthreads();
    int e = blockIdx.x * blockDim.x + threadIdx.x;
    if (e >= EE) return;
    int src, dst;
    if (is64_s) {
        const long long* p = (const long long*)ei;
        src = (int)p[e]; dst = (int)p[EE + e];
    } else {
        const int* p = (const int*)ei;
        src = p[e]; dst = p[EE + e];
    }
    int pos = atomicAdd(&g_cnt[dst], 1);
    if (pos < CAP) g_bucket[(size_t)dst * CAP + pos] = src;
}

// ---------------- fp32 -> fp16 into g_Ab self segments ----------------
__global__ void k_tofp16(const float* __restrict__ X, const float* __restrict__ h) {
    int i = blockIdx.x * blockDim.x + threadIdx.x;  // 4 elems per thread
    if (i >= NN * 64) return;
    int row = i >> 6, q = (i & 63) * 4;
    float4 vx = *(const float4*)(X + (size_t)i * 4);
    float4 vh = *(const float4*)(h + (size_t)i * 4);
    __half2* px = (__half2*)&g_Ab[(size_t)row * 1024 + 256 + q];
    px[0] = __floats2half2_rn(vx.x, vx.y);
    px[1] = __floats2half2_rn(vx.z, vx.w);
    __half2* ph = (__half2*)&g_Ab[(size_t)row * 1024 + 768 + q];
    ph[0] = __floats2half2_rn(vh.x, vh.y);
    ph[1] = __floats2half2_rn(vh.z, vh.w);
}

// ---------------- aggregation from buckets: 2-edge-parallel, 16B loads ----------------
__global__ __launch_bounds__(128) void k_agg() {
    __shared__ int sidx[128];
    __shared__ float red[64][9];   // padded to kill bank conflicts
    __shared__ int deg_s;
    int n = blockIdx.x, t = threadIdx.x;
    if (t == 0) deg_s = g_cnt[n];
    __syncthreads();
    int deg = deg_s;
    if (t == 0) g_cnt[n] = 0;      // self-clean for next call
    int cap = deg < CAP ? deg : CAP;
    const int* bkt = g_bucket + (size_t)n * CAP;
    int grp = t >> 6;
    int l = t & 63;
    const __half* basep = g_Ab + ((l < 32) ? 256 : 768);
    int q = (l & 31) * 8;
    float a0 = 0.f, a1 = 0.f, a2 = 0.f, a3 = 0.f, a4 = 0.f, a5 = 0.f, a6 = 0.f, a7 = 0.f;
    for (int bs = 0; bs < cap; bs += 128) {
        int cnt = min(128, cap - bs);
        if (t < cnt) sidx[t] = bkt[bs + t];
        __syncthreads();
        #pragma unroll 4
        for (int j = grp; j < cnt; j += 2) {
            uint4 v = *(const uint4*)(basep + (size_t)sidx[j] * 1024 + q);
            float2 f0 = __half22float2(*(__half2*)&v.x);
            float2 f1 = __half22float2(*(__half2*)&v.y);
            float2 f2 = __half22float2(*(__half2*)&v.z);
            float2 f3 = __half22float2(*(__half2*)&v.w);
            a0 += f0.x; a1 += f0.y; a2 += f1.x; a3 += f1.y;
            a4 += f2.x; a5 += f2.y; a6 += f3.x; a7 += f3.y;
        }
        __syncthreads();
    }
    if (grp == 1) {
        red[l][0] = a0; red[l][1] = a1; red[l][2] = a2; red[l][3] = a3;
        red[l][4] = a4; red[l][5] = a5; red[l][6] = a6; red[l][7] = a7;
    }
    __syncthreads();
    if (grp == 0) {
        a0 += red[l][0]; a1 += red[l][1]; a2 += red[l][2]; a3 += red[l][3];
        a4 += red[l][4]; a5 += red[l][5]; a6 += red[l][6]; a7 += red[l][7];
        float inv = 1.f / (float)(deg > 0 ? deg : 1);
        __half2 h0 = __floats2half2_rn(a0 * inv, a1 * inv);
        __half2 h1 = __floats2half2_rn(a2 * inv, a3 * inv);
        __half2 h2 = __floats2half2_rn(a4 * inv, a5 * inv);
        __half2 h3 = __floats2half2_rn(a6 * inv, a7 * inv);
        uint4 st;
        st.x = *(uint32_t*)&h0; st.y = *(uint32_t*)&h1;
        st.z = *(uint32_t*)&h2; st.w = *(uint32_t*)&h3;
        size_t o = (size_t)n * 1024 + ((l < 32) ? 0 : 512) + q;
        *(uint4*)&g_Ab[o] = st;
    }
}

// ---------------- weight packing: col order j' = 4*e + gate ----------------
__global__ void k_packWt(const float* __restrict__ Wx_l, const float* __restrict__ Wx_r,
                         const float* __restrict__ Wh_l, const float* __restrict__ Wh_r,
                         const float* __restrict__ bx_l, const float* __restrict__ bh_l,
                         const float* __restrict__ bb) {
    int idx = blockIdx.x * blockDim.x + threadIdx.x;
    if (idx >= 1024 * 1024) return;
    int d = idx & 1023;      // K row
    int jp = idx >> 10;      // output col (interleaved)
    int e = jp >> 2, k = jp & 3;
    int seg = d >> 8, dd = d & 255;
    const float* src = (seg == 0) ? Wx_l : (seg == 1) ? Wx_r : (seg == 2) ? Wh_l : Wh_r;
    float w = src[k * 65536 + dd * 256 + e];
    g_Wtb[(size_t)jp * 1024 + d] = __float2half_rn(w);
    if (d == 0)
        g_bias[jp] = bx_l[k * 256 + e] + bh_l[k * 256 + e] + bb[k * 256 + e];
}

// ---------------- mma.sync fp16 GEMM (K=1024) + fused gates ----------------
#define BM 128
#define BN 128
#define NITER 16   // 1024 / 64
#define TILE_B 16384
#define STAGE_B (2 * TILE_B)
#define DYN_SMEM (3 * STAGE_B)

#define LDSM_X4(r0, r1, r2, r3, addr) \
    asm volatile("ldmatrix.sync.aligned.m8n8.x4.shared.b16 {%0,%1,%2,%3}, [%4];" \
                 : "=r"(r0), "=r"(r1), "=r"(r2), "=r"(r3) : "r"(addr))

#define MMA16816(d, a0, a1, a2, a3, b0, b1) \
    asm volatile("mma.sync.aligned.m16n8k16.row.col.f32.f16.f16.f32 " \
                 "{%0,%1,%2,%3}, {%4,%5,%6,%7}, {%8,%9}, {%0,%1,%2,%3};" \
                 : "+f"((d)[0]), "+f"((d)[1]), "+f"((d)[2]), "+f"((d)[3]) \
                 : "r"(a0), "r"(a1), "r"(a2), "r"(a3), "r"(b0), "r"(b1))

__device__ __forceinline__ void issue_tile(uint32_t sA, uint32_t sB, int m0, int n0,
                                           int it, int tid) {
    int kk = it * 64;
    #pragma unroll
    for (int i = 0; i < 4; i++) {
        int ch = tid + i * 256;
        int row = ch >> 3, c = ch & 7;
        uint32_t so = row * 128 + ((c ^ (row & 7)) << 4);
        const __half* ga = g_Ab + (size_t)(m0 + row) * 1024 + kk + c * 8;
        unsigned sz = (m0 + row < NN) ? 16u : 0u;
        asm volatile("cp.async.cg.shared.global [%0], [%1], 16, %2;"
                     :: "r"(sA + so), "l"(ga), "r"(sz));
        const __half* gb = g_Wtb + (size_t)(n0 + row) * 1024 + kk + c * 8;
        asm volatile("cp.async.cg.shared.global [%0], [%1], 16;"
                     :: "r"(sB + so), "l"(gb));
    }
}

__device__ __forceinline__ float fsigmoid(float x) { return 1.f / (1.f + __expf(-x)); }
__device__ __forceinline__ float ftanh(float x) {
    float e = __expf(-2.f * x);
    return (1.f - e) / (1.f + e);
}

__device__ __forceinline__ void process_tile(char* smem, uint32_t sb, int tid,
                                             int m0, int n0,
                                             const float* __restrict__ cptr,
                                             const float* __restrict__ wcp,
                                             float* __restrict__ out) {
    int lane = tid & 31, wid = tid >> 5;
    int warp_m = wid & 3, warp_n = wid >> 2;
    int e0 = n0 >> 2;  // 32 features per col tile

    float acc[2][8][4];
    #pragma unroll
    for (int i = 0; i < 2; i++)
        #pragma unroll
        for (int j = 0; j < 8; j++)
            #pragma unroll
            for (int r = 0; r < 4; r++) acc[i][j][r] = 0.f;

    uint32_t sA[3], sB[3];
    #pragma unroll
    for (int s = 0; s < 3; s++) { sA[s] = sb + s * STAGE_B; sB[s] = sA[s] + TILE_B; }

    issue_tile(sA[0], sB[0], m0, n0, 0, tid);
    asm volatile("cp.async.commit_group;" ::: "memory");
    issue_tile(sA[1], sB[1], m0, n0, 1, tid);
    asm volatile("cp.async.commit_group;" ::: "memory");

    int rowA[2], rowA7[2];
    #pragma unroll
    for (int mi = 0; mi < 2; mi++) {
        int r = warp_m * 32 + mi * 16 + (lane & 15);
        rowA[mi] = r * 128;
        rowA7[mi] = r & 7;
    }
    int achk = lane >> 4;
    int local = lane & 7, quad = lane >> 3;
    int bchk = quad & 1;
    int rowB[4], rowB7[4];
    #pragma unroll
    for (int np = 0; np < 4; np++) {
        int r = warp_n * 64 + np * 16 + ((quad >> 1) << 3) + local;
        rowB[np] = r * 128;
        rowB7[np] = r & 7;
    }

    for (int it = 0; it < NITER; it++) {
        asm volatile("cp.async.wait_group 1;" ::: "memory");
        __syncthreads();
        if (it + 2 < NITER)
            issue_tile(sA[(it + 2) % 3], sB[(it + 2) % 3], m0, n0, it + 2, tid);
        asm volatile("cp.async.commit_group;" ::: "memory");
        int s = it % 3;
        uint32_t Ab = sA[s], Bb = sB[s];
        #pragma unroll
        for (int ks = 0; ks < 4; ks++) {
            uint32_t a[2][4];
            #pragma unroll
            for (int mi = 0; mi < 2; mi++) {
                uint32_t ad = Ab + rowA[mi] + ((((ks * 2 + achk)) ^ rowA7[mi]) << 4);
                LDSM_X4(a[mi][0], a[mi][1], a[mi][2], a[mi][3], ad);
            }
            #pragma unroll
            for (int np = 0; np < 4; np++) {
                uint32_t bd = Bb + rowB[np] + ((((ks * 2 + bchk)) ^ rowB7[np]) << 4);
                uint32_t t0, t1, t2, t3;
                LDSM_X4(t0, t1, t2, t3, bd);
                MMA16816(acc[0][np * 2],     a[0][0], a[0][1], a[0][2], a[0][3], t0, t1);
                MMA16816(acc[1][np * 2],     a[1][0], a[1][1], a[1][2], a[1][3], t0, t1);
                MMA16816(acc[0][np * 2 + 1], a[0][0], a[0][1], a[0][2], a[0][3], t2, t3);
                MMA16816(acc[1][np * 2 + 1], a[1][0], a[1][1], a[1][2], a[1][3], t2, t3);
            }
        }
    }
    __syncthreads();  // done with pipeline smem

    // -------- fused gate epilogue --------
    float* cbuf = (float*)smem;
    float* oO = (float*)(smem + 18432);
    float* oH = (float*)(smem + 36864);
    float* oC = (float*)(smem + 55296);
    float* wcb = (float*)(smem + 73728);

    for (int i = tid; i < 128 * 8; i += 256) {
        int r = i >> 3, q = i & 7;
        float4 v = make_float4(0.f, 0.f, 0.f, 0.f);
        if (m0 + r < NN) v = *(const float4*)(cptr + (size_t)(m0 + r) * 256 + e0 + q * 4);
        *(float4*)&cbuf[r * 36 + q * 4] = v;
    }
    if (tid < 96) wcb[tid] = wcp[(tid >> 5) * 256 + e0 + (tid & 31)];
    __syncthreads();

    int g = lane >> 2, t4 = lane & 3;
    #pragma unroll
    for (int mi = 0; mi < 2; mi++) {
        #pragma unroll
        for (int ni = 0; ni < 8; ni++) {
            int cloc = warp_n * 64 + ni * 8 + t4 * 2;
            float bias0 = __ldg(&g_bias[n0 + cloc]);
            float bias1 = __ldg(&g_bias[n0 + cloc + 1]);
            int eloc = warp_n * 16 + ni * 2 + (t4 >> 1);
            float wc0 = wcb[eloc], wc1 = wcb[32 + eloc], wc2 = wcb[64 + eloc];
            #pragma unroll
            for (int half = 0; half < 2; half++) {
                int row_loc = warp_m * 32 + mi * 16 + half * 8 + g;
                float v0 = acc[mi][ni][half * 2 + 0] + bias0;
                float v1 = acc[mi][ni][half * 2 + 1] + bias1;
                float p0 = __shfl_xor_sync(0xffffffffu, v0, 1);
                float p1 = __shfl_xor_sync(0xffffffffu, v1, 1);
                float pi, pf, pc, po;
                if ((t4 & 1) == 0) { pi = v0; pf = v1; pc = p0; po = p1; }
                else               { pi = p0; pf = p1; pc = v0; po = v1; }
                float cv = cbuf[row_loc * 36 + eloc];
                float I = fsigmoid(pi + wc0 * cv);
                float F = fsigmoid(pf + wc1 * cv);
                float T = ftanh(pc);
                float Cn = F * cv + I * T;
                float O = fsigmoid(po + wc2 * Cn);
                float Hn = O * ftanh(Cn);
                int so = row_loc * 36 + eloc;
                oO[so] = O; oH[so] = Hn; oC[so] = Cn;
            }
        }
    }
    __syncthreads();

    for (int i = tid; i < 128 * 8; i += 256) {
        int r = i >> 3, q = i & 7;
        int gr = m0 + r;
        if (gr < NN) {
            size_t go = (size_t)gr * 256 + e0 + q * 4;
            *(float4*)(out + go)                        = *(float4*)&oO[r * 36 + q * 4];
            *(float4*)(out + (size_t)NN * 256 + go)     = *(float4*)&oH[r * 36 + q * 4];
            *(float4*)(out + (size_t)2 * NN * 256 + go) = *(float4*)&oC[r * 36 + q * 4];
        }
    }
}

// virtual-tile grid: GRID_MMA blocks cover NTIL tiles (40 blocks do 2 tiles)
__global__ __launch_bounds__(256, 2) void k_mma(const float* __restrict__ cptr,
                                                const float* __restrict__ wcp,
                                                float* __restrict__ out) {
    extern __shared__ char smem[];
    uint32_t sb = smem_u32(smem);
    int tid = threadIdx.x;
    for (int t = blockIdx.x; t < NTIL; t += GRID_MMA) {
        int m0 = (t >> 3) * BM, n0 = (t & 7) * BN;
        process_tile(smem, sb, tid, m0, n0, cptr, wcp, out);
        __syncthreads();  // protect smem reuse across virtual tiles
    }
}

// ---------------- launch ----------------
extern "C" void kernel_launch(void* const* d_in, const int* in_sizes, int n_in,
                              void* d_out, int out_size) {
    const float* X    = (const float*)d_in[0];
    const void*  ei   = d_in[1];
    const float* h    = (const float*)d_in[2];
    const float* c    = (const float*)d_in[3];
    const float* Wx_l = (const float*)d_in[4];
    const float* bx_l = (const float*)d_in[5];
    const float* Wx_r = (const float*)d_in[6];
    const float* Wh_l = (const float*)d_in[7];
    const float* bh_l = (const float*)d_in[8];
    const float* Wh_r = (const float*)d_in[9];
    const float* wc   = (const float*)d_in[10];
    const float* b    = (const float*)d_in[11];
    float* out = (float*)d_out;

    static int inited = 0;
    static cudaStream_t s1;
    static cudaEvent_t ev0, evA, evW;
    if (!inited) {
        cudaFuncSetAttribute(k_mma, cudaFuncAttributeMaxDynamicSharedMemorySize, DYN_SMEM);
        cudaStreamCreateWithFlags(&s1, cudaStreamNonBlocking);
        cudaEventCreateWithFlags(&ev0, cudaEventDisableTiming);
        cudaEventCreateWithFlags(&evA, cudaEventDisableTiming);
        cudaEventCreateWithFlags(&evW, cudaEventDisableTiming);
        inited = 1;
    }

    // fork side stream: self-feature convert + weight pack (independent of edges)
    cudaEventRecord(ev0, 0);
    cudaStreamWaitEvent(s1, ev0, 0);
    k_tofp16<<<(NN * 64 + 255) / 256, 256, 0, s1>>>(X, h);
    cudaEventRecord(evA, s1);  // g_Ab self segments ready
    k_packWt<<<(1024 * 1024 + 255) / 256, 256, 0, s1>>>(Wx_l, Wx_r, Wh_l, Wh_r, bx_l, bh_l, b);
    cudaEventRecord(evW, s1);

    // main stream: fused edge pass -> aggregation -> GEMM
    k_edges<<<(EE + 255) / 256, 256>>>(ei);
    cudaStreamWaitEvent(0, evA, 0);   // agg gathers from g_Ab self segments
    k_agg<<<NN, 128>>>();
    cudaStreamWaitEvent(0, evW, 0);   // mma reads g_Wtb
    k_mma<<<GRID_MMA, 256, DYN_SMEM>>>(c, wc, out);
}

// round 16
// speedup vs baseline: 1.0381x; 1.0381x over previous
#include <cuda_runtime.h>
#include <cuda_fp16.h>
#include <math.h>
#include <stdint.h>

#define NN 10000
#define EE 320000
#define CAP 192   // bucket slots per node; deg ~ Binom(320k, 1e-4), mean 32, P(>192) ~ 0
#define NTILM 79
#define NTILN 8

// k_prep block partition
#define PB_EDGE 1250            // EE/256
#define PB_CONV 2500            // NN*64/256
#define PB_PACK 4096            // 1024*1024/256
#define PB_TOTAL (PB_EDGE + PB_CONV + PB_PACK)

// ---------------- scratch (static device globals; no allocation) ----------------
__device__ int   g_cnt[NN];                   // zero-init at load; k_agg re-zeros after use
__device__ int   g_bucket[(size_t)NN * CAP];  // per-node src lists
__device__ __half g_Ab[(size_t)NN * 1024];    // [aggX | X | aggH | h] fp16
__device__ __half g_Wtb[(size_t)1024 * 1024]; // W^T: row j'(out col), K contiguous
__device__ float g_bias[1024];                // bx_l + bh_l + b, in j' order

__device__ __forceinline__ uint32_t smem_u32(const void* p) {
    uint32_t a;
    asm("{ .reg .u64 t; cvta.to.shared.u64 t, %1; cvt.u32.u64 %0, t; }" : "=r"(a) : "l"(p));
    return a;
}

// ---------------- fused prologue: edges + tofp16 + packWt in one grid ----------------
__global__ void k_prep(const void* __restrict__ ei,
                       const float* __restrict__ X, const float* __restrict__ h,
                       const float* __restrict__ Wx_l, const float* __restrict__ Wx_r,
                       const float* __restrict__ Wh_l, const float* __restrict__ Wh_r,
                       const float* __restrict__ bx_l, const float* __restrict__ bh_l,
                       const float* __restrict__ bb) {
    int blk = blockIdx.x;
    if (blk < PB_EDGE) {
        // ---- edge pass: dtype detect + scatter into buckets ----
        __shared__ int is64_s;
        if (threadIdx.x == 0) {
            const unsigned* w = (const unsigned*)ei;
            unsigned bad = 0;
            #pragma unroll
            for (int k = 0; k < 64; k++) bad |= w[2 * k + 1];  // high words if int64
            is64_s = (bad == 0) ? 1 : 0;
        }
        __syncthreads();
        int e = blk * 256 + threadIdx.x;
        if (e >= EE) return;
        int src, dst;
        if (is64_s) {
            const long long* p = (const long long*)ei;
            src = (int)p[e]; dst = (int)p[EE + e];
        } else {
            const int* p = (const int*)ei;
            src = p[e]; dst = p[EE + e];
        }
        int pos = atomicAdd(&g_cnt[dst], 1);
        if (pos < CAP) g_bucket[(size_t)dst * CAP + pos] = src;
    } else if (blk < PB_EDGE + PB_CONV) {
        // ---- fp32 -> fp16 into g_Ab self segments ----
        int i = (blk - PB_EDGE) * 256 + threadIdx.x;  // 4 elems per thread
        if (i >= NN * 64) return;
        int row = i >> 6, q = (i & 63) * 4;
        float4 vx = *(const float4*)(X + (size_t)i * 4);
        float4 vh = *(const float4*)(h + (size_t)i * 4);
        __half2* px = (__half2*)&g_Ab[(size_t)row * 1024 + 256 + q];
        px[0] = __floats2half2_rn(vx.x, vx.y);
        px[1] = __floats2half2_rn(vx.z, vx.w);
        __half2* ph = (__half2*)&g_Ab[(size_t)row * 1024 + 768 + q];
        ph[0] = __floats2half2_rn(vh.x, vh.y);
        ph[1] = __floats2half2_rn(vh.z, vh.w);
    } else {
        // ---- weight packing: col order j' = 4*e + gate ----
        int idx = (blk - PB_EDGE - PB_CONV) * 256 + threadIdx.x;
        if (idx >= 1024 * 1024) return;
        int d = idx & 1023;      // K row
        int jp = idx >> 10;      // output col (interleaved)
        int e = jp >> 2, k = jp & 3;
        int seg = d >> 8, dd = d & 255;
        const float* src = (seg == 0) ? Wx_l : (seg == 1) ? Wx_r : (seg == 2) ? Wh_l : Wh_r;
        float w = src[k * 65536 + dd * 256 + e];
        g_Wtb[(size_t)jp * 1024 + d] = __float2half_rn(w);
        if (d == 0)
            g_bias[jp] = bx_l[k * 256 + e] + bh_l[k * 256 + e] + bb[k * 256 + e];
    }
}

// ---------------- aggregation from buckets: 2-edge-parallel, 16B loads ----------------
__global__ __launch_bounds__(128) void k_agg() {
    __shared__ int sidx[128];
    __shared__ float red[64][9];   // padded to kill bank conflicts
    __shared__ int deg_s;
    int n = blockIdx.x, t = threadIdx.x;
    if (t == 0) deg_s = g_cnt[n];
    __syncthreads();
    int deg = deg_s;
    if (t == 0) g_cnt[n] = 0;      // self-clean for next call
    int cap = deg < CAP ? deg : CAP;
    const int* bkt = g_bucket + (size_t)n * CAP;
    int grp = t >> 6;
    int l = t & 63;
    const __half* basep = g_Ab + ((l < 32) ? 256 : 768);
    int q = (l & 31) * 8;
    float a0 = 0.f, a1 = 0.f, a2 = 0.f, a3 = 0.f, a4 = 0.f, a5 = 0.f, a6 = 0.f, a7 = 0.f;
    for (int bs = 0; bs < cap; bs += 128) {
        int cnt = min(128, cap - bs);
        if (t < cnt) sidx[t] = bkt[bs + t];
        __syncthreads();
        #pragma unroll 4
        for (int j = grp; j < cnt; j += 2) {
            uint4 v = *(const uint4*)(basep + (size_t)sidx[j] * 1024 + q);
            float2 f0 = __half22float2(*(__half2*)&v.x);
            float2 f1 = __half22float2(*(__half2*)&v.y);
            float2 f2 = __half22float2(*(__half2*)&v.z);
            float2 f3 = __half22float2(*(__half2*)&v.w);
            a0 += f0.x; a1 += f0.y; a2 += f1.x; a3 += f1.y;
            a4 += f2.x; a5 += f2.y; a6 += f3.x; a7 += f3.y;
        }
        __syncthreads();
    }
    if (grp == 1) {
        red[l][0] = a0; red[l][1] = a1; red[l][2] = a2; red[l][3] = a3;
        red[l][4] = a4; red[l][5] = a5; red[l][6] = a6; red[l][7] = a7;
    }
    __syncthreads();
    if (grp == 0) {
        a0 += red[l][0]; a1 += red[l][1]; a2 += red[l][2]; a3 += red[l][3];
        a4 += red[l][4]; a5 += red[l][5]; a6 += red[l][6]; a7 += red[l][7];
        float inv = 1.f / (float)(deg > 0 ? deg : 1);
        __half2 h0 = __floats2half2_rn(a0 * inv, a1 * inv);
        __half2 h1 = __floats2half2_rn(a2 * inv, a3 * inv);
        __half2 h2 = __floats2half2_rn(a4 * inv, a5 * inv);
        __half2 h3 = __floats2half2_rn(a6 * inv, a7 * inv);
        uint4 st;
        st.x = *(uint32_t*)&h0; st.y = *(uint32_t*)&h1;
        st.z = *(uint32_t*)&h2; st.w = *(uint32_t*)&h3;
        size_t o = (size_t)n * 1024 + ((l < 32) ? 0 : 512) + q;
        *(uint4*)&g_Ab[o] = st;
    }
}

// ---------------- mma.sync fp16 GEMM (K=1024) + fused gates ----------------
#define BM 128
#define BN 128
#define NITER 16   // 1024 / 64
#define TILE_B 16384
#define STAGE_B (2 * TILE_B)
#define DYN_SMEM (3 * STAGE_B)

#define LDSM_X4(r0, r1, r2, r3, addr) \
    asm volatile("ldmatrix.sync.aligned.m8n8.x4.shared.b16 {%0,%1,%2,%3}, [%4];" \
                 : "=r"(r0), "=r"(r1), "=r"(r2), "=r"(r3) : "r"(addr))

#define MMA16816(d, a0, a1, a2, a3, b0, b1) \
    asm volatile("mma.sync.aligned.m16n8k16.row.col.f32.f16.f16.f32 " \
                 "{%0,%1,%2,%3}, {%4,%5,%6,%7}, {%8,%9}, {%0,%1,%2,%3};" \
                 : "+f"((d)[0]), "+f"((d)[1]), "+f"((d)[2]), "+f"((d)[3]) \
                 : "r"(a0), "r"(a1), "r"(a2), "r"(a3), "r"(b0), "r"(b1))

__device__ __forceinline__ void issue_tile(uint32_t sA, uint32_t sB, int m0, int n0,
                                           int it, int tid) {
    int kk = it * 64;
    #pragma unroll
    for (int i = 0; i < 4; i++) {
        int ch = tid + i * 256;
        int row = ch >> 3, c = ch & 7;
        uint32_t so = row * 128 + ((c ^ (row & 7)) << 4);
        const __half* ga = g_Ab + (size_t)(m0 + row) * 1024 + kk + c * 8;
        unsigned sz = (m0 + row < NN) ? 16u : 0u;
        asm volatile("cp.async.cg.shared.global [%0], [%1], 16, %2;"
                     :: "r"(sA + so), "l"(ga), "r"(sz));
        const __half* gb = g_Wtb + (size_t)(n0 + row) * 1024 + kk + c * 8;
        asm volatile("cp.async.cg.shared.global [%0], [%1], 16;"
                     :: "r"(sB + so), "l"(gb));
    }
}

__device__ __forceinline__ float fsigmoid(float x) { return 1.f / (1.f + __expf(-x)); }
__device__ __forceinline__ float ftanh(float x) {
    float e = __expf(-2.f * x);
    return (1.f - e) / (1.f + e);
}

__global__ __launch_bounds__(256, 2) void k_mma(const float* __restrict__ cptr,
                                                const float* __restrict__ wcp,
                                                float* __restrict__ out) {
    extern __shared__ char smem[];
    uint32_t sb = smem_u32(smem);
    int tid = threadIdx.x;
    int lane = tid & 31, wid = tid >> 5;
    int warp_m = wid & 3, warp_n = wid >> 2;
    int m0 = blockIdx.y * BM, n0 = blockIdx.x * BN;
    int e0 = n0 >> 2;  // 32 features per col tile

    float acc[2][8][4];
    #pragma unroll
    for (int i = 0; i < 2; i++)
        #pragma unroll
        for (int j = 0; j < 8; j++)
            #pragma unroll
            for (int r = 0; r < 4; r++) acc[i][j][r] = 0.f;

    uint32_t sA[3], sB[3];
    #pragma unroll
    for (int s = 0; s < 3; s++) { sA[s] = sb + s * STAGE_B; sB[s] = sA[s] + TILE_B; }

    issue_tile(sA[0], sB[0], m0, n0, 0, tid);
    asm volatile("cp.async.commit_group;" ::: "memory");
    issue_tile(sA[1], sB[1], m0, n0, 1, tid);
    asm volatile("cp.async.commit_group;" ::: "memory");

    int rowA[2], rowA7[2];
    #pragma unroll
    for (int mi = 0; mi < 2; mi++) {
        int r = warp_m * 32 + mi * 16 + (lane & 15);
        rowA[mi] = r * 128;
        rowA7[mi] = r & 7;
    }
    int achk = lane >> 4;
    int local = lane & 7, quad = lane >> 3;
    int bchk = quad & 1;
    int rowB[4], rowB7[4];
    #pragma unroll
    for (int np = 0; np < 4; np++) {
        int r = warp_n * 64 + np * 16 + ((quad >> 1) << 3) + local;
        rowB[np] = r * 128;
        rowB7[np] = r & 7;
    }

    for (int it = 0; it < NITER; it++) {
        asm volatile("cp.async.wait_group 1;" ::: "memory");
        __syncthreads();
        if (it + 2 < NITER)
            issue_tile(sA[(it + 2) % 3], sB[(it + 2) % 3], m0, n0, it + 2, tid);
        asm volatile("cp.async.commit_group;" ::: "memory");
        int s = it % 3;
        uint32_t Ab = sA[s], Bb = sB[s];
        #pragma unroll
        for (int ks = 0; ks < 4; ks++) {
            uint32_t a[2][4];
            #pragma unroll
            for (int mi = 0; mi < 2; mi++) {
                uint32_t ad = Ab + rowA[mi] + ((((ks * 2 + achk)) ^ rowA7[mi]) << 4);
                LDSM_X4(a[mi][0], a[mi][1], a[mi][2], a[mi][3], ad);
            }
            #pragma unroll
            for (int np = 0; np < 4; np++) {
                uint32_t bd = Bb + rowB[np] + ((((ks * 2 + bchk)) ^ rowB7[np]) << 4);
                uint32_t t0, t1, t2, t3;
                LDSM_X4(t0, t1, t2, t3, bd);
                MMA16816(acc[0][np * 2],     a[0][0], a[0][1], a[0][2], a[0][3], t0, t1);
                MMA16816(acc[1][np * 2],     a[1][0], a[1][1], a[1][2], a[1][3], t0, t1);
                MMA16816(acc[0][np * 2 + 1], a[0][0], a[0][1], a[0][2], a[0][3], t2, t3);
                MMA16816(acc[1][np * 2 + 1], a[1][0], a[1][1], a[1][2], a[1][3], t2, t3);
            }
        }
    }
    __syncthreads();  // done with pipeline smem

    // -------- fused gate epilogue --------
    float* cbuf = (float*)smem;
    float* oO = (float*)(smem + 18432);
    float* oH = (float*)(smem + 36864);
    float* oC = (float*)(smem + 55296);
    float* wcb = (float*)(smem + 73728);

    for (int i = tid; i < 128 * 8; i += 256) {
        int r = i >> 3, q = i & 7;
        float4 v = make_float4(0.f, 0.f, 0.f, 0.f);
        if (m0 + r < NN) v = *(const float4*)(cptr + (size_t)(m0 + r) * 256 + e0 + q * 4);
        *(float4*)&cbuf[r * 36 + q * 4] = v;
    }
    if (tid < 96) wcb[tid] = wcp[(tid >> 5) * 256 + e0 + (tid & 31)];
    __syncthreads();

    int g = lane >> 2, t4 = lane & 3;
    #pragma unroll
    for (int mi = 0; mi < 2; mi++) {
        #pragma unroll
        for (int ni = 0; ni < 8; ni++) {
            int cloc = warp_n * 64 + ni * 8 + t4 * 2;
            float bias0 = __ldg(&g_bias[n0 + cloc]);
            float bias1 = __ldg(&g_bias[n0 + cloc + 1]);
            int eloc = warp_n * 16 + ni * 2 + (t4 >> 1);
            float wc0 = wcb[eloc], wc1 = wcb[32 + eloc], wc2 = wcb[64 + eloc];
            #pragma unroll
            for (int half = 0; half < 2; half++) {
                int row_loc = warp_m * 32 + mi * 16 + half * 8 + g;
                float v0 = acc[mi][ni][half * 2 + 0] + bias0;
                float v1 = acc[mi][ni][half * 2 + 1] + bias1;
                float p0 = __shfl_xor_sync(0xffffffffu, v0, 1);
                float p1 = __shfl_xor_sync(0xffffffffu, v1, 1);
                float pi, pf, pc, po;
                if ((t4 & 1) == 0) { pi = v0; pf = v1; pc = p0; po = p1; }
                else               { pi = p0; pf = p1; pc = v0; po = v1; }
                float cv = cbuf[row_loc * 36 + eloc];
                float I = fsigmoid(pi + wc0 * cv);
                float F = fsigmoid(pf + wc1 * cv);
                float T = ftanh(pc);
                float Cn = F * cv + I * T;
                float O = fsigmoid(po + wc2 * Cn);
                float Hn = O * ftanh(Cn);
                int so = row_loc * 36 + eloc;
                oO[so] = O; oH[so] = Hn; oC[so] = Cn;
            }
        }
    }
    __syncthreads();

    for (int i = tid; i < 128 * 8; i += 256) {
        int r = i >> 3, q = i & 7;
        int gr = m0 + r;
        if (gr < NN) {
            size_t go = (size_t)gr * 256 + e0 + q * 4;
            *(float4*)(out + go)                        = *(float4*)&oO[r * 36 + q * 4];
            *(float4*)(out + (size_t)NN * 256 + go)     = *(float4*)&oH[r * 36 + q * 4];
            *(float4*)(out + (size_t)2 * NN * 256 + go) = *(float4*)&oC[r * 36 + q * 4];
        }
    }
}

// ---------------- launch: 3 kernels, one stream, no events ----------------
extern "C" void kernel_launch(void* const* d_in, const int* in_sizes, int n_in,
                              void* d_out, int out_size) {
    const float* X    = (const float*)d_in[0];
    const void*  ei   = d_in[1];
    const float* h    = (const float*)d_in[2];
    const float* c    = (const float*)d_in[3];
    const float* Wx_l = (const float*)d_in[4];
    const float* bx_l = (const float*)d_in[5];
    const float* Wx_r = (const float*)d_in[6];
    const float* Wh_l = (const float*)d_in[7];
    const float* bh_l = (const float*)d_in[8];
    const float* Wh_r = (const float*)d_in[9];
    const float* wc   = (const float*)d_in[10];
    const float* b    = (const float*)d_in[11];
    float* out = (float*)d_out;

    static int inited = 0;
    if (!inited) {
        cudaFuncSetAttribute(k_mma, cudaFuncAttributeMaxDynamicSharedMemorySize, DYN_SMEM);
        inited = 1;
    }

    k_prep<<<PB_TOTAL, 256>>>(ei, X, h, Wx_l, Wx_r, Wh_l, Wh_r, bx_l, bh_l, b);
    k_agg<<<NN, 128>>>();
    k_mma<<<dim3(NTILN, NTILM), 256, DYN_SMEM>>>(c, wc, out);
}